// round 4
// baseline (speedup 1.0000x reference)
#include <cuda_runtime.h>
#include <cstddef>

#define IN_F   2048
#define OUT_F  4096
#define BATCHN 131072

#define IN_F4  (IN_F / 4)      // 512 float4 per row
#define NPART  64              // row partials for wsum

// Deterministic scratch (no allocations allowed).
__device__ float4 g_wpart[NPART * IN_F4];   // 512 KB
__device__ float4 g_wsum4[IN_F4];
__device__ float  g_bsum;

// ---------------------------------------------------------------------------
// Kernel 1: partial column sums of weight [OUT_F, IN_F], vectorized.
// grid = (4, 64), block = 128. Block (bx, by): float4-cols [bx*128, bx*128+128),
// rows [by*64, by*64+64). LDG.128, coalesced, 4 independent fp32 chains,
// unroll 8 -> MLP ~8 per thread.
// ---------------------------------------------------------------------------
__global__ __launch_bounds__(128) void wsum_partial(const float4* __restrict__ w4) {
    const int col4 = blockIdx.x * 128 + threadIdx.x;
    const int part = blockIdx.y;
    const int r0   = part * (OUT_F / NPART);       // 64 rows per partial

    float ax = 0.f, ay = 0.f, az = 0.f, aw = 0.f;
#pragma unroll 8
    for (int r = 0; r < OUT_F / NPART; r++) {
        const float4 v = w4[(size_t)(r0 + r) * IN_F4 + col4];
        ax += v.x; ay += v.y; az += v.z; aw += v.w;
    }
    float4 o; o.x = ax; o.y = ay; o.z = az; o.w = aw;
    g_wpart[part * IN_F4 + col4] = o;
}

// ---------------------------------------------------------------------------
// Kernel 2: finalize. Blocks 0..3 (128 thr) reduce the 64 partials per
// float4-column into g_wsum4. Block 4 tree-reduces bias into g_bsum.
// Fully deterministic ordering.
// ---------------------------------------------------------------------------
__global__ __launch_bounds__(128) void finalize(const float* __restrict__ bias) {
    if (blockIdx.x < 4) {
        const int col4 = blockIdx.x * 128 + threadIdx.x;
        float ax = 0.f, ay = 0.f, az = 0.f, aw = 0.f;
#pragma unroll 8
        for (int p = 0; p < NPART; p++) {
            const float4 v = g_wpart[p * IN_F4 + col4];
            ax += v.x; ay += v.y; az += v.z; aw += v.w;
        }
        float4 o; o.x = ax; o.y = ay; o.z = az; o.w = aw;
        g_wsum4[col4] = o;
    } else {
        __shared__ float sh[128];
        float s = 0.f;
        for (int i = threadIdx.x; i < OUT_F; i += 128) s += bias[i];
        sh[threadIdx.x] = s;
        __syncthreads();
        for (int stride = 64; stride > 0; stride >>= 1) {
            if (threadIdx.x < (unsigned)stride) sh[threadIdx.x] += sh[threadIdx.x + stride];
            __syncthreads();
        }
        if (threadIdx.x == 0) g_bsum = sh[0];
    }
}

// ---------------------------------------------------------------------------
// Kernel 3: out[row] = dot(x[row,:], w_sum) + b_sum.
// Persistent single-wave: grid = 148*4 CTAs, __launch_bounds__(256,4) pins
// 4 CTAs/SM residency (regs <= 64). w_sum staged once per CTA into 8 KB
// shared. Warp-strided loop over 4-row tasks; per row each lane issues 16
// independent LDG.128 (streaming, evict-first) against the x row, 4 fp32
// FMA chains, shfl_xor warp reduce.
// ---------------------------------------------------------------------------
static constexpr int ROWS_PER_TASK = 4;
static constexpr int DOT_BLOCKS    = 148 * 4;                 // 592, one wave
static constexpr int TOTAL_WARPS   = DOT_BLOCKS * 8;          // 4736
static constexpr int NUM_TASKS     = BATCHN / ROWS_PER_TASK;  // 32768

__global__ __launch_bounds__(256, 4) void dot_kernel(const float4* __restrict__ x4,
                                                     float* __restrict__ out) {
    __shared__ float4 shw[IN_F4];  // 8 KB

    const int tid = threadIdx.x;
#pragma unroll
    for (int i = tid; i < IN_F4; i += 256) shw[i] = g_wsum4[i];
    __syncthreads();

    const float bsum = g_bsum;
    const int lane  = tid & 31;
    const int gwarp = blockIdx.x * 8 + (tid >> 5);

    for (int task = gwarp; task < NUM_TASKS; task += TOTAL_WARPS) {
        const int row0 = task * ROWS_PER_TASK;
#pragma unroll
        for (int r = 0; r < ROWS_PER_TASK; r++) {
            const int row = row0 + r;
            const float4* __restrict__ xr = x4 + (size_t)row * IN_F4;

            float ax = 0.f, ay = 0.f, az = 0.f, aw = 0.f;
#pragma unroll
            for (int i = 0; i < 16; i++) {
                const float4 xv = __ldcs(xr + i * 32 + lane);  // 512 B/warp, evict-first
                const float4 wv = shw[i * 32 + lane];
                ax = fmaf(xv.x, wv.x, ax);
                ay = fmaf(xv.y, wv.y, ay);
                az = fmaf(xv.z, wv.z, az);
                aw = fmaf(xv.w, wv.w, aw);
            }
            float acc = (ax + ay) + (az + aw);
#pragma unroll
            for (int off = 16; off > 0; off >>= 1)
                acc += __shfl_xor_sync(0xffffffffu, acc, off);
            if (lane == 0) out[row] = acc + bsum;
        }
    }
}

// ---------------------------------------------------------------------------
extern "C" void kernel_launch(void* const* d_in, const int* in_sizes, int n_in,
                              void* d_out, int out_size) {
    const float* x      = (const float*)d_in[0];   // [BATCHN, IN_F]
    const float* weight = (const float*)d_in[1];   // [OUT_F, IN_F]
    const float* bias   = (const float*)d_in[2];   // [OUT_F]
    float* out          = (float*)d_out;           // [BATCHN, 1]

    (void)in_sizes; (void)n_in; (void)out_size;

    dim3 g1(IN_F4 / 128, NPART);                   // (4, 64) = 256 blocks
    wsum_partial<<<g1, 128>>>(reinterpret_cast<const float4*>(weight));

    finalize<<<5, 128>>>(bias);

    dot_kernel<<<DOT_BLOCKS, 256>>>(reinterpret_cast<const float4*>(x), out);
}